// round 2
// baseline (speedup 1.0000x reference)
#include <cuda_runtime.h>
#include <math.h>

// Problem shape (fixed by the dataset)
#define BB 16
#define NN 1024
#define HH 1280
#define DD 256
#define EPSV 1e-8f

// Output segment offsets (elements), tuple flattened in order, float32
#define OFF_CH   0LL                                  // charged_kin  (B,H,3)
#define OFF_NEUT (OFF_CH   + (long long)BB*HH*3)      // neut_kin     (B,H,3)
#define OFF_PC   (OFF_NEUT + (long long)BB*HH*3)      // proxy_is_charged (B,H)
#define OFF_EM   (OFF_PC   + (long long)BB*HH)        // proxy_em_frac    (B,H)
#define OFF_MM   (OFF_EM   + (long long)BB*HH)        // inc_times_node_feat (B,H,D)
#define OFF_NFS  (OFF_MM   + (long long)BB*HH*DD)     // node_feat_sum (B,D)

// Scratch: per-(b,n) precomputed weight vectors
__device__ float g_w   [BB*NN];
__device__ float g_weta[BB*NN];
__device__ float g_wsin[BB*NN];
__device__ float g_wcos[BB*NN];
__device__ float g_wem [BB*NN];

// ---------------------------------------------------------------------------
// 1) Precompute w = e_raw*is_topo and its products (B*N = 16384 elems, trivial)
// ---------------------------------------------------------------------------
__global__ void prep_kernel(const float* __restrict__ e_raw,
                            const float* __restrict__ eta_raw,
                            const float* __restrict__ phi,
                            const float* __restrict__ em_frac,
                            const int*   __restrict__ is_topo) {
    int i = blockIdx.x * blockDim.x + threadIdx.x;
    if (i >= BB * NN) return;
    float w = e_raw[i] * (float)is_topo[i];
    float s, c;
    sincosf(phi[i], &s, &c);
    g_w[i]    = w;
    g_weta[i] = w * eta_raw[i];
    g_wsin[i] = w * s;
    g_wcos[i] = w * c;
    g_wem[i]  = w * em_frac[i];
}

// ---------------------------------------------------------------------------
// 2) Per-(b,h) row reductions: one warp per row of pred_inc.
//    Produces charged_kin, neut_kin, proxy_is_charged, proxy_em_frac.
// ---------------------------------------------------------------------------
__global__ void row_kernel(const float* __restrict__ pred_inc,
                           const float* __restrict__ track_pt,
                           const float* __restrict__ track_eta,
                           const float* __restrict__ track_phi,
                           const int*   __restrict__ is_track,
                           float* __restrict__ out) {
    int warps_per_blk = blockDim.x >> 5;
    int row = blockIdx.x * warps_per_blk + (threadIdx.x >> 5);  // b*H + h
    if (row >= BB * HH) return;
    int lane = threadIdx.x & 31;
    int b = row / HH;
    int h = row % HH;

    const float4* p4 = (const float4*)(pred_inc + (size_t)row * NN);
    const float4* w4 = (const float4*)(g_w    + b * NN);
    const float4* e4 = (const float4*)(g_weta + b * NN);
    const float4* s4 = (const float4*)(g_wsin + b * NN);
    const float4* c4 = (const float4*)(g_wcos + b * NN);
    const float4* m4 = (const float4*)(g_wem  + b * NN);

    float s0 = 0.f, s1 = 0.f, s2 = 0.f, s3 = 0.f, s4v = 0.f;
    #pragma unroll 4
    for (int i = lane; i < NN / 4; i += 32) {
        float4 p = p4[i];
        float4 w = w4[i];
        s0 = fmaf(p.x, w.x, s0); s0 = fmaf(p.y, w.y, s0);
        s0 = fmaf(p.z, w.z, s0); s0 = fmaf(p.w, w.w, s0);
        float4 e = e4[i];
        s1 = fmaf(p.x, e.x, s1); s1 = fmaf(p.y, e.y, s1);
        s1 = fmaf(p.z, e.z, s1); s1 = fmaf(p.w, e.w, s1);
        float4 s = s4[i];
        s2 = fmaf(p.x, s.x, s2); s2 = fmaf(p.y, s.y, s2);
        s2 = fmaf(p.z, s.z, s2); s2 = fmaf(p.w, s.w, s2);
        float4 c = c4[i];
        s3 = fmaf(p.x, c.x, s3); s3 = fmaf(p.y, c.y, s3);
        s3 = fmaf(p.z, c.z, s3); s3 = fmaf(p.w, c.w, s3);
        float4 m = m4[i];
        s4v = fmaf(p.x, m.x, s4v); s4v = fmaf(p.y, m.y, s4v);
        s4v = fmaf(p.z, m.z, s4v); s4v = fmaf(p.w, m.w, s4v);
    }
    #pragma unroll
    for (int o = 16; o > 0; o >>= 1) {
        s0  += __shfl_xor_sync(0xFFFFFFFFu, s0,  o);
        s1  += __shfl_xor_sync(0xFFFFFFFFu, s1,  o);
        s2  += __shfl_xor_sync(0xFFFFFFFFu, s2,  o);
        s3  += __shfl_xor_sync(0xFFFFFFFFu, s3,  o);
        s4v += __shfl_xor_sync(0xFFFFFFFFu, s4v, o);
    }
    if (lane == 0) {
        float inv = 1.f / (s0 + EPSV);
        bool  pc  = (h < NN) && (is_track[b * NN + h] != 0);
        float nm  = pc ? 0.f : 1.f;

        float ke  = log1pf(fmaxf(s0, 0.f));
        float eta = s1 * inv * (1.f / 3.0f);
        float ph  = atan2f(s2 * inv, s3 * inv);
        float em  = s4v * inv;

        long long r3 = (long long)row * 3;
        // charged_kin: is_track-gated track features (h<N) else 0
        float cpt = 0.f, ceta = 0.f, cphi = 0.f;
        if (pc) {
            cpt  = track_pt [b * NN + h];
            ceta = track_eta[b * NN + h];
            cphi = track_phi[b * NN + h];
        }
        out[OFF_CH + r3 + 0] = cpt;
        out[OFF_CH + r3 + 1] = ceta;
        out[OFF_CH + r3 + 2] = cphi;
        out[OFF_NEUT + r3 + 0] = ke  * nm;
        out[OFF_NEUT + r3 + 1] = eta * nm;
        out[OFF_NEUT + r3 + 2] = ph  * nm;
        out[OFF_PC + row] = pc ? 1.f : 0.f;
        out[OFF_EM + row] = em;
    }
}

// ---------------------------------------------------------------------------
// 3) Batched GEMM: C[b,h,d] = sum_n pred_inc[b,h,n] * node_feat[b,n,d]
//    128x64 tile, BK=16, 256 threads, 8x4 per-thread microtile, fp32.
// ---------------------------------------------------------------------------
#define GBM 128
#define GBN 64
#define GBK 16
#define GTM 8
#define GTN 4

__global__ __launch_bounds__(256)
void gemm_kernel(const float* __restrict__ A,   // [B][H][N]
                 const float* __restrict__ Bm,  // [B][N][D]
                 float* __restrict__ C) {       // out + OFF_MM, [B][H][D]
    int b  = blockIdx.z;
    int m0 = blockIdx.y * GBM;
    int n0 = blockIdx.x * GBN;
    const float* Ab = A  + (size_t)b * HH * NN;
    const float* Bb = Bm + (size_t)b * NN * DD;

    __shared__ float As[GBK][GBM + 4];
    __shared__ float Bs[GBK][GBN];

    float acc[GTM][GTN];
    #pragma unroll
    for (int i = 0; i < GTM; i++)
        #pragma unroll
        for (int j = 0; j < GTN; j++) acc[i][j] = 0.f;

    int tid = threadIdx.x;
    int tx = tid % 16;   // n-group
    int ty = tid / 16;   // m-group

    int ar  = tid >> 2;  // 0..63: A row within tile (pass adds 64)
    int ac4 = tid & 3;   // 0..3:  float4 within the 16-wide k row
    int br  = tid >> 4;  // 0..15: B row (k)
    int bc4 = tid & 15;  // 0..15: float4 within 64-wide n row

    for (int k0 = 0; k0 < NN; k0 += GBK) {
        #pragma unroll
        for (int p = 0; p < 2; p++) {
            int r = ar + p * 64;
            float4 v = *(const float4*)(Ab + (size_t)(m0 + r) * NN + k0 + ac4 * 4);
            As[ac4 * 4 + 0][r] = v.x;
            As[ac4 * 4 + 1][r] = v.y;
            As[ac4 * 4 + 2][r] = v.z;
            As[ac4 * 4 + 3][r] = v.w;
        }
        float4 w = *(const float4*)(Bb + (size_t)(k0 + br) * DD + n0 + bc4 * 4);
        *(float4*)(&Bs[br][bc4 * 4]) = w;
        __syncthreads();

        #pragma unroll
        for (int k = 0; k < GBK; k++) {
            float a[GTM], bv[GTN];
            #pragma unroll
            for (int i = 0; i < GTM; i++) a[i] = As[k][ty * GTM + i];
            #pragma unroll
            for (int j = 0; j < GTN; j++) bv[j] = Bs[k][tx * GTN + j];
            #pragma unroll
            for (int i = 0; i < GTM; i++)
                #pragma unroll
                for (int j = 0; j < GTN; j++)
                    acc[i][j] = fmaf(a[i], bv[j], acc[i][j]);
        }
        __syncthreads();
    }

    float* Cb = C + (size_t)b * HH * DD;
    #pragma unroll
    for (int i = 0; i < GTM; i++) {
        float4 v = make_float4(acc[i][0], acc[i][1], acc[i][2], acc[i][3]);
        *(float4*)(Cb + (size_t)(m0 + ty * GTM + i) * DD + n0 + tx * GTN) = v;
    }
}

// ---------------------------------------------------------------------------
// 4) node_feat_sum[b,d] = sum_n node_feat[b,n,d]
//    grid (D/32, B), 256 threads = 8 n-slices x 32 d-lanes
// ---------------------------------------------------------------------------
__global__ void nfs_kernel(const float* __restrict__ nf, float* __restrict__ out) {
    int b = blockIdx.y;
    int d = blockIdx.x * 32 + (threadIdx.x & 31);
    int g = threadIdx.x >> 5;  // 0..7
    float s = 0.f;
    const float* base = nf + (size_t)b * NN * DD + d;
    for (int n = g; n < NN; n += 8) s += base[(size_t)n * DD];
    __shared__ float sm[8][33];
    sm[g][threadIdx.x & 31] = s;
    __syncthreads();
    if (g == 0) {
        int l = threadIdx.x & 31;
        float t = sm[0][l] + sm[1][l] + sm[2][l] + sm[3][l]
                + sm[4][l] + sm[5][l] + sm[6][l] + sm[7][l];
        out[OFF_NFS + (long long)b * DD + d] = t;
    }
}

// ---------------------------------------------------------------------------
extern "C" void kernel_launch(void* const* d_in, const int* in_sizes, int n_in,
                              void* d_out, int out_size) {
    const float* pred_inc  = (const float*)d_in[0];
    const float* node_feat = (const float*)d_in[1];
    const float* e_raw     = (const float*)d_in[2];
    const float* eta_raw   = (const float*)d_in[3];
    const float* phi       = (const float*)d_in[4];
    const float* em_frac   = (const float*)d_in[5];
    const float* track_pt  = (const float*)d_in[6];
    const float* track_eta = (const float*)d_in[7];
    const float* track_phi = (const float*)d_in[8];
    const int*   is_track  = (const int*)d_in[9];
    const int*   is_topo   = (const int*)d_in[10];
    float* out = (float*)d_out;

    // 1) tiny precompute
    prep_kernel<<<(BB * NN + 255) / 256, 256>>>(e_raw, eta_raw, phi, em_frac, is_topo);

    // 2) per-row reductions (8 warps/block)
    {
        int rows = BB * HH;
        int warps_per_blk = 8;
        int blocks = (rows + warps_per_blk - 1) / warps_per_blk;
        row_kernel<<<blocks, warps_per_blk * 32>>>(pred_inc, track_pt, track_eta,
                                                   track_phi, is_track, out);
    }

    // 3) GEMM
    {
        dim3 grid(DD / GBN, HH / GBM, BB);
        gemm_kernel<<<grid, 256>>>(pred_inc, node_feat, out + OFF_MM);
    }

    // 4) node_feat_sum
    {
        dim3 grid(DD / 32, BB);
        nfs_kernel<<<grid, 256>>>(node_feat, out);
    }
}

// round 4
// speedup vs baseline: 2.1128x; 2.1128x over previous
#include <cuda_runtime.h>
#include <math.h>
#include <stdint.h>

// Problem shape (fixed by the dataset)
#define BB 16
#define NN 1024
#define HH 1280
#define DD 256
#define EPSV 1e-8f

// Output segment offsets (elements), tuple flattened in order, float32
#define OFF_CH   0LL
#define OFF_NEUT (OFF_CH   + (long long)BB*HH*3)
#define OFF_PC   (OFF_NEUT + (long long)BB*HH*3)
#define OFF_EM   (OFF_PC   + (long long)BB*HH)
#define OFF_MM   (OFF_EM   + (long long)BB*HH)
#define OFF_NFS  (OFF_MM   + (long long)BB*HH*DD)

// Device scratch
__device__ float g_w   [BB*NN];
__device__ float g_weta[BB*NN];
__device__ float g_wsin[BB*NN];
__device__ float g_wcos[BB*NN];
__device__ float g_wem [BB*NN];
#define NSPL 32
__device__ float g_nfs_part[BB*NSPL*DD];

// ---------------------------------------------------------------------------
// PTX helpers (baseline PTX only — no sm_100a-gated features)
// ---------------------------------------------------------------------------
__device__ __forceinline__ uint32_t smem_u32(const void* p) {
    return (uint32_t)__cvta_generic_to_shared(p);
}
__device__ __forceinline__ void cp16(uint32_t dst, const void* src) {
    asm volatile("cp.async.cg.shared.global [%0], [%1], 16;"
                 :: "r"(dst), "l"(src) : "memory");
}
__device__ __forceinline__ void cp_commit() {
    asm volatile("cp.async.commit_group;" ::: "memory");
}
template <int N>
__device__ __forceinline__ void cp_wait() {
    asm volatile("cp.async.wait_group %0;" :: "n"(N) : "memory");
}
__device__ __forceinline__ uint32_t f2tf32(float x) {
    uint32_t r;
    asm("cvt.rna.tf32.f32 %0, %1;" : "=r"(r) : "f"(x));
    return r;
}
__device__ __forceinline__ void mma_tf32(float* c, const uint32_t* a, const uint32_t* b) {
    asm volatile(
        "mma.sync.aligned.m16n8k8.row.col.f32.tf32.tf32.f32 "
        "{%0,%1,%2,%3}, {%4,%5,%6,%7}, {%8,%9}, {%0,%1,%2,%3};"
        : "+f"(c[0]), "+f"(c[1]), "+f"(c[2]), "+f"(c[3])
        : "r"(a[0]), "r"(a[1]), "r"(a[2]), "r"(a[3]), "r"(b[0]), "r"(b[1]));
}

// ---------------------------------------------------------------------------
// 1) Precompute w = e_raw*is_topo and its products
// ---------------------------------------------------------------------------
__global__ void prep_kernel(const float* __restrict__ e_raw,
                            const float* __restrict__ eta_raw,
                            const float* __restrict__ phi,
                            const float* __restrict__ em_frac,
                            const int*   __restrict__ is_topo) {
    int i = blockIdx.x * blockDim.x + threadIdx.x;
    if (i >= BB * NN) return;
    float w = e_raw[i] * (float)is_topo[i];
    float s, c;
    sincosf(phi[i], &s, &c);
    g_w[i]    = w;
    g_weta[i] = w * eta_raw[i];
    g_wsin[i] = w * s;
    g_wcos[i] = w * c;
    g_wem[i]  = w * em_frac[i];
}

// ---------------------------------------------------------------------------
// 2) node_feat_sum: split-N partials for occupancy, then tiny reduce
// ---------------------------------------------------------------------------
__global__ void nfs_part_kernel(const float* __restrict__ nf) {
    int b = blockIdx.y, s = blockIdx.x, d = threadIdx.x;  // 256 threads
    const float* base = nf + (size_t)b * NN * DD + (size_t)s * (NN / NSPL) * DD + d;
    float acc = 0.f;
    #pragma unroll
    for (int i = 0; i < NN / NSPL; i++) acc += base[(size_t)i * DD];
    g_nfs_part[((size_t)b * NSPL + s) * DD + d] = acc;
}
__global__ void nfs_final_kernel(float* __restrict__ out) {
    int b = blockIdx.x, d = threadIdx.x;
    float s = 0.f;
    #pragma unroll
    for (int t = 0; t < NSPL; t++) s += g_nfs_part[((size_t)b * NSPL + t) * DD + d];
    out[OFF_NFS + (size_t)b * DD + d] = s;
}

// ---------------------------------------------------------------------------
// 3) Per-(b,h) row reductions (unchanged, known correct)
// ---------------------------------------------------------------------------
__global__ void row_kernel(const float* __restrict__ pred_inc,
                           const float* __restrict__ track_pt,
                           const float* __restrict__ track_eta,
                           const float* __restrict__ track_phi,
                           const int*   __restrict__ is_track,
                           float* __restrict__ out) {
    int warps_per_blk = blockDim.x >> 5;
    int row = blockIdx.x * warps_per_blk + (threadIdx.x >> 5);
    if (row >= BB * HH) return;
    int lane = threadIdx.x & 31;
    int b = row / HH;
    int h = row % HH;

    const float4* p4 = (const float4*)(pred_inc + (size_t)row * NN);
    const float4* w4 = (const float4*)(g_w    + b * NN);
    const float4* e4 = (const float4*)(g_weta + b * NN);
    const float4* s4 = (const float4*)(g_wsin + b * NN);
    const float4* c4 = (const float4*)(g_wcos + b * NN);
    const float4* m4 = (const float4*)(g_wem  + b * NN);

    float s0 = 0.f, s1 = 0.f, s2 = 0.f, s3 = 0.f, s4v = 0.f;
    #pragma unroll 4
    for (int i = lane; i < NN / 4; i += 32) {
        float4 p = p4[i];
        float4 w = w4[i];
        s0 = fmaf(p.x, w.x, s0); s0 = fmaf(p.y, w.y, s0);
        s0 = fmaf(p.z, w.z, s0); s0 = fmaf(p.w, w.w, s0);
        float4 e = e4[i];
        s1 = fmaf(p.x, e.x, s1); s1 = fmaf(p.y, e.y, s1);
        s1 = fmaf(p.z, e.z, s1); s1 = fmaf(p.w, e.w, s1);
        float4 s = s4[i];
        s2 = fmaf(p.x, s.x, s2); s2 = fmaf(p.y, s.y, s2);
        s2 = fmaf(p.z, s.z, s2); s2 = fmaf(p.w, s.w, s2);
        float4 c = c4[i];
        s3 = fmaf(p.x, c.x, s3); s3 = fmaf(p.y, c.y, s3);
        s3 = fmaf(p.z, c.z, s3); s3 = fmaf(p.w, c.w, s3);
        float4 m = m4[i];
        s4v = fmaf(p.x, m.x, s4v); s4v = fmaf(p.y, m.y, s4v);
        s4v = fmaf(p.z, m.z, s4v); s4v = fmaf(p.w, m.w, s4v);
    }
    #pragma unroll
    for (int o = 16; o > 0; o >>= 1) {
        s0  += __shfl_xor_sync(0xFFFFFFFFu, s0,  o);
        s1  += __shfl_xor_sync(0xFFFFFFFFu, s1,  o);
        s2  += __shfl_xor_sync(0xFFFFFFFFu, s2,  o);
        s3  += __shfl_xor_sync(0xFFFFFFFFu, s3,  o);
        s4v += __shfl_xor_sync(0xFFFFFFFFu, s4v, o);
    }
    if (lane == 0) {
        float inv = 1.f / (s0 + EPSV);
        bool  pc  = (h < NN) && (is_track[b * NN + h] != 0);
        float nm  = pc ? 0.f : 1.f;

        float ke  = log1pf(fmaxf(s0, 0.f));
        float eta = s1 * inv * (1.f / 3.0f);
        float ph  = atan2f(s2 * inv, s3 * inv);
        float em  = s4v * inv;

        long long r3 = (long long)row * 3;
        float cpt = 0.f, ceta = 0.f, cphi = 0.f;
        if (pc) {
            cpt  = track_pt [b * NN + h];
            ceta = track_eta[b * NN + h];
            cphi = track_phi[b * NN + h];
        }
        out[OFF_CH + r3 + 0] = cpt;
        out[OFF_CH + r3 + 1] = ceta;
        out[OFF_CH + r3 + 2] = cphi;
        out[OFF_NEUT + r3 + 0] = ke  * nm;
        out[OFF_NEUT + r3 + 1] = eta * nm;
        out[OFF_NEUT + r3 + 2] = ph  * nm;
        out[OFF_PC + row] = pc ? 1.f : 0.f;
        out[OFF_EM + row] = em;
    }
}

// ---------------------------------------------------------------------------
// 4) tf32 mma.sync GEMM: C[b,m,d] = sum_n A[b,m,n] * B[b,n,d]
//    Block tile 128x128, BK=16, 256 threads (8 warps, 2x4, warp tile 64x32),
//    2-stage cp.async double buffer. B consumed col-major direct from [n][d].
// ---------------------------------------------------------------------------
#define BM 128
#define BN 128
#define BK 16
#define APAD 20        // floats per A smem row (conflict-free frag loads)
#define BPAD 136       // floats per B smem row (stride*k ≡ 8k mod 32)
#define A_ELE (BM * APAD)       // 2560
#define B_ELE (BK * BPAD)       // 2176
#define STG_ELE (A_ELE + B_ELE) // 4736 floats = 18944 B

__global__ __launch_bounds__(256)
void gemm_mma_kernel(const float* __restrict__ A,   // [B][H][N]
                     const float* __restrict__ Bm,  // [B][N][D]
                     float* __restrict__ C) {       // [B][H][D]
    __shared__ __align__(16) float smem[2 * STG_ELE];

    int tid  = threadIdx.x;
    int wid  = tid >> 5;
    int lane = tid & 31;
    int gid  = lane >> 2;   // groupID 0..7
    int tig  = lane & 3;    // thread-in-group 0..3
    int warp_m = wid & 1;   // 0..1
    int warp_n = wid >> 1;  // 0..3

    int b  = blockIdx.z;
    int m0 = blockIdx.y * BM;
    int n0 = blockIdx.x * BN;

    const float* Ab = A  + ((size_t)b * HH + m0) * NN;
    const float* Bb = Bm + (size_t)b * NN * DD + n0;

    // loader indices
    int ar  = tid >> 2;   // 0..63 (A row; second pass +64)
    int ac4 = tid & 3;    // 0..3  (float4 within 16-wide k row)
    int brk = tid >> 5;   // 0..7  (B k-row; second pass +8)
    int bc  = tid & 31;   // 0..31 (float4 within 128-wide n row)

    float acc[4][4][4];
    #pragma unroll
    for (int i = 0; i < 4; i++)
        #pragma unroll
        for (int j = 0; j < 4; j++)
            #pragma unroll
            for (int k = 0; k < 4; k++) acc[i][j][k] = 0.f;

    auto load_tile = [&](int t, int s) {
        float* as = smem + s * STG_ELE;
        float* bs = as + A_ELE;
        int k0 = t * BK;
        cp16(smem_u32(as + ar * APAD + ac4 * 4),
             Ab + (size_t)ar * NN + k0 + ac4 * 4);
        cp16(smem_u32(as + (ar + 64) * APAD + ac4 * 4),
             Ab + (size_t)(ar + 64) * NN + k0 + ac4 * 4);
        cp16(smem_u32(bs + brk * BPAD + bc * 4),
             Bb + (size_t)(k0 + brk) * DD + bc * 4);
        cp16(smem_u32(bs + (brk + 8) * BPAD + bc * 4),
             Bb + (size_t)(k0 + brk + 8) * DD + bc * 4);
        cp_commit();
    };

    load_tile(0, 0);

    const int NT = NN / BK;  // 64
    for (int t = 0; t < NT; t++) {
        if (t + 1 < NT) {
            load_tile(t + 1, (t + 1) & 1);
            cp_wait<1>();
        } else {
            cp_wait<0>();
        }
        __syncthreads();

        const float* as = smem + (t & 1) * STG_ELE;
        const float* bs = as + A_ELE;

        #pragma unroll
        for (int kk = 0; kk < BK; kk += 8) {
            uint32_t af[4][4];
            #pragma unroll
            for (int mf = 0; mf < 4; mf++) {
                int m = warp_m * 64 + mf * 16 + gid;
                af[mf][0] = f2tf32(as[(size_t)m * APAD + kk + tig]);
                af[mf][1] = f2tf32(as[(size_t)(m + 8) * APAD + kk + tig]);
                af[mf][2] = f2tf32(as[(size_t)m * APAD + kk + tig + 4]);
                af[mf][3] = f2tf32(as[(size_t)(m + 8) * APAD + kk + tig + 4]);
            }
            uint32_t bf[4][2];
            #pragma unroll
            for (int nf = 0; nf < 4; nf++) {
                int n = warp_n * 32 + nf * 8 + gid;
                bf[nf][0] = f2tf32(bs[(size_t)(kk + tig) * BPAD + n]);
                bf[nf][1] = f2tf32(bs[(size_t)(kk + tig + 4) * BPAD + n]);
            }
            #pragma unroll
            for (int mf = 0; mf < 4; mf++)
                #pragma unroll
                for (int nf = 0; nf < 4; nf++)
                    mma_tf32(acc[mf][nf], af[mf], bf[nf]);
        }
        __syncthreads();
    }

    // Epilogue: C fragment layout m16n8 -> (row=gid(+8), col=tig*2(+1))
    float* Cb = C + ((size_t)b * HH + m0) * DD + n0;
    #pragma unroll
    for (int mf = 0; mf < 4; mf++) {
        int r0 = warp_m * 64 + mf * 16 + gid;
        #pragma unroll
        for (int nf = 0; nf < 4; nf++) {
            int cc = warp_n * 32 + nf * 8 + tig * 2;
            *(float2*)(Cb + (size_t)r0 * DD + cc) =
                make_float2(acc[mf][nf][0], acc[mf][nf][1]);
            *(float2*)(Cb + (size_t)(r0 + 8) * DD + cc) =
                make_float2(acc[mf][nf][2], acc[mf][nf][3]);
        }
    }
}

// ---------------------------------------------------------------------------
extern "C" void kernel_launch(void* const* d_in, const int* in_sizes, int n_in,
                              void* d_out, int out_size) {
    const float* pred_inc  = (const float*)d_in[0];
    const float* node_feat = (const float*)d_in[1];
    const float* e_raw     = (const float*)d_in[2];
    const float* eta_raw   = (const float*)d_in[3];
    const float* phi       = (const float*)d_in[4];
    const float* em_frac   = (const float*)d_in[5];
    const float* track_pt  = (const float*)d_in[6];
    const float* track_eta = (const float*)d_in[7];
    const float* track_phi = (const float*)d_in[8];
    const int*   is_track  = (const int*)d_in[9];
    const int*   is_topo   = (const int*)d_in[10];
    float* out = (float*)d_out;

    prep_kernel<<<(BB * NN + 255) / 256, 256>>>(e_raw, eta_raw, phi, em_frac, is_topo);

    {
        dim3 grid(NSPL, BB);
        nfs_part_kernel<<<grid, DD>>>(node_feat);
    }
    nfs_final_kernel<<<BB, DD>>>(out);

    {
        int rows = BB * HH;
        int warps_per_blk = 8;
        int blocks = (rows + warps_per_blk - 1) / warps_per_blk;
        row_kernel<<<blocks, warps_per_blk * 32>>>(pred_inc, track_pt, track_eta,
                                                   track_phi, is_track, out);
    }

    {
        dim3 grid(DD / BN, HH / BM, BB);
        gemm_mma_kernel<<<grid, 256>>>(pred_inc, node_feat, out + OFF_MM);
    }
}

// round 5
// speedup vs baseline: 2.3425x; 1.1088x over previous
#include <cuda_runtime.h>
#include <math.h>
#include <stdint.h>

// Problem shape (fixed by the dataset)
#define BB 16
#define NN 1024
#define HH 1280
#define DD 256
#define EPSV 1e-8f

// Output segment offsets (elements), tuple flattened in order, float32
#define OFF_CH   0LL
#define OFF_NEUT (OFF_CH   + (long long)BB*HH*3)
#define OFF_PC   (OFF_NEUT + (long long)BB*HH*3)
#define OFF_EM   (OFF_PC   + (long long)BB*HH)
#define OFF_MM   (OFF_EM   + (long long)BB*HH)
#define OFF_NFS  (OFF_MM   + (long long)BB*HH*DD)

// Device scratch
__device__ float g_w   [BB*NN];
__device__ float g_weta[BB*NN];
__device__ float g_wsin[BB*NN];
__device__ float g_wcos[BB*NN];
__device__ float g_wem [BB*NN];
#define NSPL 32
__device__ float g_nfs_part[BB*NSPL*DD];

// ---------------------------------------------------------------------------
// PTX helpers (baseline PTX only — no sm_100a-gated features)
// ---------------------------------------------------------------------------
__device__ __forceinline__ uint32_t smem_u32(const void* p) {
    return (uint32_t)__cvta_generic_to_shared(p);
}
__device__ __forceinline__ void cp16(uint32_t dst, const void* src) {
    asm volatile("cp.async.cg.shared.global [%0], [%1], 16;"
                 :: "r"(dst), "l"(src) : "memory");
}
__device__ __forceinline__ void cp_commit() {
    asm volatile("cp.async.commit_group;" ::: "memory");
}
template <int N>
__device__ __forceinline__ void cp_wait() {
    asm volatile("cp.async.wait_group %0;" :: "n"(N) : "memory");
}
__device__ __forceinline__ uint32_t f2tf32(float x) {
    uint32_t r;
    asm("cvt.rna.tf32.f32 %0, %1;" : "=r"(r) : "f"(x));
    return r;
}
__device__ __forceinline__ void mma_tf32(float* c, const uint32_t* a, const uint32_t* b) {
    asm volatile(
        "mma.sync.aligned.m16n8k8.row.col.f32.tf32.tf32.f32 "
        "{%0,%1,%2,%3}, {%4,%5,%6,%7}, {%8,%9}, {%0,%1,%2,%3};"
        : "+f"(c[0]), "+f"(c[1]), "+f"(c[2]), "+f"(c[3])
        : "r"(a[0]), "r"(a[1]), "r"(a[2]), "r"(a[3]), "r"(b[0]), "r"(b[1]));
}

// ---------------------------------------------------------------------------
// 1) Precompute w = e_raw*is_topo and its products
// ---------------------------------------------------------------------------
__global__ void prep_kernel(const float* __restrict__ e_raw,
                            const float* __restrict__ eta_raw,
                            const float* __restrict__ phi,
                            const float* __restrict__ em_frac,
                            const int*   __restrict__ is_topo) {
    int i = blockIdx.x * blockDim.x + threadIdx.x;
    if (i >= BB * NN) return;
    float w = e_raw[i] * (float)is_topo[i];
    float s, c;
    sincosf(phi[i], &s, &c);
    g_w[i]    = w;
    g_weta[i] = w * eta_raw[i];
    g_wsin[i] = w * s;
    g_wcos[i] = w * c;
    g_wem[i]  = w * em_frac[i];
}

// ---------------------------------------------------------------------------
// 2) node_feat_sum: split-N partials, then tiny reduce
// ---------------------------------------------------------------------------
__global__ void nfs_part_kernel(const float* __restrict__ nf) {
    int b = blockIdx.y, s = blockIdx.x, d = threadIdx.x;  // 256 threads
    const float* base = nf + (size_t)b * NN * DD + (size_t)s * (NN / NSPL) * DD + d;
    float acc = 0.f;
    #pragma unroll
    for (int i = 0; i < NN / NSPL; i++) acc += base[(size_t)i * DD];
    g_nfs_part[((size_t)b * NSPL + s) * DD + d] = acc;
}
__global__ void nfs_final_kernel(float* __restrict__ out) {
    int b = blockIdx.x, d = threadIdx.x;
    float s = 0.f;
    #pragma unroll
    for (int t = 0; t < NSPL; t++) s += g_nfs_part[((size_t)b * NSPL + t) * DD + d];
    out[OFF_NFS + (size_t)b * DD + d] = s;
}

// ---------------------------------------------------------------------------
// 3) Per-(b,h) row reductions: one warp handles TWO rows sharing weight loads
// ---------------------------------------------------------------------------
__global__ __launch_bounds__(256, 5)
void row_kernel(const float* __restrict__ pred_inc,
                const float* __restrict__ track_pt,
                const float* __restrict__ track_eta,
                const float* __restrict__ track_phi,
                const int*   __restrict__ is_track,
                float* __restrict__ out) {
    int pr = blockIdx.x * (blockDim.x >> 5) + (threadIdx.x >> 5);  // row-pair
    if (pr >= (BB * HH) / 2) return;
    int lane = threadIdx.x & 31;
    int row0 = pr * 2;                 // rows row0, row0+1 (same b: HH is even)
    int b = row0 / HH;

    const float4* p4 = (const float4*)(pred_inc + (size_t)row0 * NN);
    const float4* q4 = (const float4*)(pred_inc + (size_t)(row0 + 1) * NN);
    const float4* w4 = (const float4*)(g_w    + b * NN);
    const float4* e4 = (const float4*)(g_weta + b * NN);
    const float4* s4 = (const float4*)(g_wsin + b * NN);
    const float4* c4 = (const float4*)(g_wcos + b * NN);
    const float4* m4 = (const float4*)(g_wem  + b * NN);

    float a0 = 0.f, a1 = 0.f, a2 = 0.f, a3 = 0.f, a4 = 0.f;
    float b0 = 0.f, b1 = 0.f, b2 = 0.f, b3 = 0.f, b4 = 0.f;
    #pragma unroll 2
    for (int i = lane; i < NN / 4; i += 32) {
        float4 p = p4[i];
        float4 q = q4[i];
        float4 w = w4[i];
        a0 = fmaf(p.x, w.x, a0); a0 = fmaf(p.y, w.y, a0);
        a0 = fmaf(p.z, w.z, a0); a0 = fmaf(p.w, w.w, a0);
        b0 = fmaf(q.x, w.x, b0); b0 = fmaf(q.y, w.y, b0);
        b0 = fmaf(q.z, w.z, b0); b0 = fmaf(q.w, w.w, b0);
        float4 e = e4[i];
        a1 = fmaf(p.x, e.x, a1); a1 = fmaf(p.y, e.y, a1);
        a1 = fmaf(p.z, e.z, a1); a1 = fmaf(p.w, e.w, a1);
        b1 = fmaf(q.x, e.x, b1); b1 = fmaf(q.y, e.y, b1);
        b1 = fmaf(q.z, e.z, b1); b1 = fmaf(q.w, e.w, b1);
        float4 s = s4[i];
        a2 = fmaf(p.x, s.x, a2); a2 = fmaf(p.y, s.y, a2);
        a2 = fmaf(p.z, s.z, a2); a2 = fmaf(p.w, s.w, a2);
        b2 = fmaf(q.x, s.x, b2); b2 = fmaf(q.y, s.y, b2);
        b2 = fmaf(q.z, s.z, b2); b2 = fmaf(q.w, s.w, b2);
        float4 c = c4[i];
        a3 = fmaf(p.x, c.x, a3); a3 = fmaf(p.y, c.y, a3);
        a3 = fmaf(p.z, c.z, a3); a3 = fmaf(p.w, c.w, a3);
        b3 = fmaf(q.x, c.x, b3); b3 = fmaf(q.y, c.y, b3);
        b3 = fmaf(q.z, c.z, b3); b3 = fmaf(q.w, c.w, b3);
        float4 m = m4[i];
        a4 = fmaf(p.x, m.x, a4); a4 = fmaf(p.y, m.y, a4);
        a4 = fmaf(p.z, m.z, a4); a4 = fmaf(p.w, m.w, a4);
        b4 = fmaf(q.x, m.x, b4); b4 = fmaf(q.y, m.y, b4);
        b4 = fmaf(q.z, m.z, b4); b4 = fmaf(q.w, m.w, b4);
    }
    #pragma unroll
    for (int o = 16; o > 0; o >>= 1) {
        a0 += __shfl_xor_sync(0xFFFFFFFFu, a0, o);
        a1 += __shfl_xor_sync(0xFFFFFFFFu, a1, o);
        a2 += __shfl_xor_sync(0xFFFFFFFFu, a2, o);
        a3 += __shfl_xor_sync(0xFFFFFFFFu, a3, o);
        a4 += __shfl_xor_sync(0xFFFFFFFFu, a4, o);
        b0 += __shfl_xor_sync(0xFFFFFFFFu, b0, o);
        b1 += __shfl_xor_sync(0xFFFFFFFFu, b1, o);
        b2 += __shfl_xor_sync(0xFFFFFFFFu, b2, o);
        b3 += __shfl_xor_sync(0xFFFFFFFFu, b3, o);
        b4 += __shfl_xor_sync(0xFFFFFFFFu, b4, o);
    }
    if (lane == 0) {
        #pragma unroll
        for (int rr = 0; rr < 2; rr++) {
            int   row = row0 + rr;
            int   h   = row % HH;
            float s0  = rr ? b0 : a0;
            float s1  = rr ? b1 : a1;
            float s2  = rr ? b2 : a2;
            float s3  = rr ? b3 : a3;
            float s4v = rr ? b4 : a4;

            float inv = 1.f / (s0 + EPSV);
            bool  pc  = (h < NN) && (is_track[b * NN + h] != 0);
            float nm  = pc ? 0.f : 1.f;

            float ke  = log1pf(fmaxf(s0, 0.f));
            float eta = s1 * inv * (1.f / 3.0f);
            float ph  = atan2f(s2 * inv, s3 * inv);
            float em  = s4v * inv;

            long long r3 = (long long)row * 3;
            float cpt = 0.f, ceta = 0.f, cphi = 0.f;
            if (pc) {
                cpt  = track_pt [b * NN + h];
                ceta = track_eta[b * NN + h];
                cphi = track_phi[b * NN + h];
            }
            out[OFF_CH + r3 + 0] = cpt;
            out[OFF_CH + r3 + 1] = ceta;
            out[OFF_CH + r3 + 2] = cphi;
            out[OFF_NEUT + r3 + 0] = ke  * nm;
            out[OFF_NEUT + r3 + 1] = eta * nm;
            out[OFF_NEUT + r3 + 2] = ph  * nm;
            out[OFF_PC + row] = pc ? 1.f : 0.f;
            out[OFF_EM + row] = em;
        }
    }
}

// ---------------------------------------------------------------------------
// 4) tf32 mma.sync GEMM: block 128x128, BK=16, 128 threads (4 warps, 2x2),
//    warp tile 64x64 -> LDS/mma ratio 1.0 (was 1.5). 2-stage cp.async.
// ---------------------------------------------------------------------------
#define BM 128
#define BN 128
#define BK 16
#define APAD 20
#define BPAD 136
#define A_ELE (BM * APAD)
#define B_ELE (BK * BPAD)
#define STG_ELE (A_ELE + B_ELE)

__global__ __launch_bounds__(128)
void gemm_mma_kernel(const float* __restrict__ A,   // [B][H][N]
                     const float* __restrict__ Bm,  // [B][N][D]
                     float* __restrict__ C) {       // [B][H][D]
    __shared__ __align__(16) float smem[2 * STG_ELE];

    int tid  = threadIdx.x;
    int wid  = tid >> 5;        // 0..3
    int lane = tid & 31;
    int gid  = lane >> 2;       // 0..7
    int tig  = lane & 3;        // 0..3
    int warp_m = wid & 1;       // 0..1
    int warp_n = wid >> 1;      // 0..1

    int b  = blockIdx.z;
    int m0 = blockIdx.y * BM;
    int n0 = blockIdx.x * BN;

    const float* Ab = A  + ((size_t)b * HH + m0) * NN;
    const float* Bb = Bm + (size_t)b * NN * DD + n0;

    // loader indices (128 threads)
    int ar  = tid >> 2;   // 0..31 (A row; +32 per pass, 4 passes)
    int ac4 = tid & 3;    // 0..3
    int bk  = tid >> 5;   // 0..3  (B k-row; +4 per pass, 4 passes)
    int bc  = tid & 31;   // 0..31

    float acc[4][8][4];
    #pragma unroll
    for (int i = 0; i < 4; i++)
        #pragma unroll
        for (int j = 0; j < 8; j++)
            #pragma unroll
            for (int k = 0; k < 4; k++) acc[i][j][k] = 0.f;

    auto load_tile = [&](int t, int s) {
        float* as = smem + s * STG_ELE;
        float* bs = as + A_ELE;
        int k0 = t * BK;
        #pragma unroll
        for (int i = 0; i < 4; i++) {
            int r = ar + i * 32;
            cp16(smem_u32(as + r * APAD + ac4 * 4),
                 Ab + (size_t)r * NN + k0 + ac4 * 4);
        }
        #pragma unroll
        for (int i = 0; i < 4; i++) {
            int k = bk + i * 4;
            cp16(smem_u32(bs + k * BPAD + bc * 4),
                 Bb + (size_t)(k0 + k) * DD + bc * 4);
        }
        cp_commit();
    };

    load_tile(0, 0);

    const int NT = NN / BK;  // 64
    for (int t = 0; t < NT; t++) {
        if (t + 1 < NT) {
            load_tile(t + 1, (t + 1) & 1);
            cp_wait<1>();
        } else {
            cp_wait<0>();
        }
        __syncthreads();

        const float* as = smem + (t & 1) * STG_ELE;
        const float* bs = as + A_ELE;

        #pragma unroll
        for (int kk = 0; kk < BK; kk += 8) {
            uint32_t bf[8][2];
            #pragma unroll
            for (int nf = 0; nf < 8; nf++) {
                int n = warp_n * 64 + nf * 8 + gid;
                bf[nf][0] = f2tf32(bs[(size_t)(kk + tig) * BPAD + n]);
                bf[nf][1] = f2tf32(bs[(size_t)(kk + tig + 4) * BPAD + n]);
            }
            #pragma unroll
            for (int mf = 0; mf < 4; mf++) {
                int m = warp_m * 64 + mf * 16 + gid;
                uint32_t af[4];
                af[0] = f2tf32(as[(size_t)m * APAD + kk + tig]);
                af[1] = f2tf32(as[(size_t)(m + 8) * APAD + kk + tig]);
                af[2] = f2tf32(as[(size_t)m * APAD + kk + tig + 4]);
                af[3] = f2tf32(as[(size_t)(m + 8) * APAD + kk + tig + 4]);
                #pragma unroll
                for (int nf = 0; nf < 8; nf++)
                    mma_tf32(acc[mf][nf], af, bf[nf]);
            }
        }
        __syncthreads();
    }

    // Epilogue
    float* Cb = C + ((size_t)b * HH + m0) * DD + n0;
    #pragma unroll
    for (int mf = 0; mf < 4; mf++) {
        int r0 = warp_m * 64 + mf * 16 + gid;
        #pragma unroll
        for (int nf = 0; nf < 8; nf++) {
            int cc = warp_n * 64 + nf * 8 + tig * 2;
            *(float2*)(Cb + (size_t)r0 * DD + cc) =
                make_float2(acc[mf][nf][0], acc[mf][nf][1]);
            *(float2*)(Cb + (size_t)(r0 + 8) * DD + cc) =
                make_float2(acc[mf][nf][2], acc[mf][nf][3]);
        }
    }
}

// ---------------------------------------------------------------------------
extern "C" void kernel_launch(void* const* d_in, const int* in_sizes, int n_in,
                              void* d_out, int out_size) {
    const float* pred_inc  = (const float*)d_in[0];
    const float* node_feat = (const float*)d_in[1];
    const float* e_raw     = (const float*)d_in[2];
    const float* eta_raw   = (const float*)d_in[3];
    const float* phi       = (const float*)d_in[4];
    const float* em_frac   = (const float*)d_in[5];
    const float* track_pt  = (const float*)d_in[6];
    const float* track_eta = (const float*)d_in[7];
    const float* track_phi = (const float*)d_in[8];
    const int*   is_track  = (const int*)d_in[9];
    const int*   is_topo   = (const int*)d_in[10];
    float* out = (float*)d_out;

    prep_kernel<<<(BB * NN + 255) / 256, 256>>>(e_raw, eta_raw, phi, em_frac, is_topo);

    {
        dim3 grid(NSPL, BB);
        nfs_part_kernel<<<grid, DD>>>(node_feat);
    }
    nfs_final_kernel<<<BB, DD>>>(out);

    {
        int pairs = (BB * HH) / 2;
        int warps_per_blk = 8;
        int blocks = (pairs + warps_per_blk - 1) / warps_per_blk;
        row_kernel<<<blocks, warps_per_blk * 32>>>(pred_inc, track_pt, track_eta,
                                                   track_phi, is_track, out);
    }

    {
        dim3 grid(DD / BN, HH / BM, BB);
        gemm_mma_kernel<<<grid, 128>>>(pred_inc, node_feat, out + OFF_MM);
    }
}

// round 6
// speedup vs baseline: 2.9904x; 1.2766x over previous
#include <cuda_runtime.h>
#include <cuda_fp16.h>
#include <math.h>
#include <stdint.h>

// Problem shape (fixed by the dataset)
#define BB 16
#define NN 1024
#define HH 1280
#define DD 256
#define EPSV 1e-8f

// Output segment offsets (elements), tuple flattened in order, float32
#define OFF_CH   0LL
#define OFF_NEUT (OFF_CH   + (long long)BB*HH*3)
#define OFF_PC   (OFF_NEUT + (long long)BB*HH*3)
#define OFF_EM   (OFF_PC   + (long long)BB*HH)
#define OFF_MM   (OFF_EM   + (long long)BB*HH)
#define OFF_NFS  (OFF_MM   + (long long)BB*HH*DD)

// Device scratch
__device__ float  g_w   [BB*NN];
__device__ float  g_weta[BB*NN];
__device__ float  g_wsin[BB*NN];
__device__ float  g_wcos[BB*NN];
__device__ float  g_wem [BB*NN];
__device__ __half g_ah[(size_t)BB*HH*NN];   // pred_inc as fp16 [b][h][n]  (40 MB)
__device__ __half g_bh[(size_t)BB*DD*NN];   // node_feat as fp16 [b][d][n] (8 MB)
#define NSPL 32
__device__ float  g_nfs_part[BB*NSPL*DD];

// ---------------------------------------------------------------------------
// PTX helpers (baseline PTX only)
// ---------------------------------------------------------------------------
__device__ __forceinline__ uint32_t smem_u32(const void* p) {
    return (uint32_t)__cvta_generic_to_shared(p);
}
__device__ __forceinline__ void cp16(uint32_t dst, const void* src) {
    asm volatile("cp.async.cg.shared.global [%0], [%1], 16;"
                 :: "r"(dst), "l"(src) : "memory");
}
__device__ __forceinline__ void cp_commit() {
    asm volatile("cp.async.commit_group;" ::: "memory");
}
template <int N>
__device__ __forceinline__ void cp_wait() {
    asm volatile("cp.async.wait_group %0;" :: "n"(N) : "memory");
}
__device__ __forceinline__ void mma_f16(float* c, const uint32_t* a, const uint32_t* b) {
    asm volatile(
        "mma.sync.aligned.m16n8k16.row.col.f32.f16.f16.f32 "
        "{%0,%1,%2,%3}, {%4,%5,%6,%7}, {%8,%9}, {%0,%1,%2,%3};"
        : "+f"(c[0]), "+f"(c[1]), "+f"(c[2]), "+f"(c[3])
        : "r"(a[0]), "r"(a[1]), "r"(a[2]), "r"(a[3]), "r"(b[0]), "r"(b[1]));
}

// ---------------------------------------------------------------------------
// 1) Precompute w = e_raw*is_topo and its products
// ---------------------------------------------------------------------------
__global__ void prep_kernel(const float* __restrict__ e_raw,
                            const float* __restrict__ eta_raw,
                            const float* __restrict__ phi,
                            const float* __restrict__ em_frac,
                            const int*   __restrict__ is_topo) {
    int i = blockIdx.x * blockDim.x + threadIdx.x;
    if (i >= BB * NN) return;
    float w = e_raw[i] * (float)is_topo[i];
    float s, c;
    sincosf(phi[i], &s, &c);
    g_w[i]    = w;
    g_weta[i] = w * eta_raw[i];
    g_wsin[i] = w * s;
    g_wcos[i] = w * c;
    g_wem[i]  = w * em_frac[i];
}

// ---------------------------------------------------------------------------
// 2) Transpose node_feat [b,n,d] -> g_bh fp16 [b,d,n]; fused nfs partials
// ---------------------------------------------------------------------------
__global__ void transpose_kernel(const float* __restrict__ nf) {
    __shared__ float tile[32][33];
    int b  = blockIdx.z;
    int n0 = blockIdx.x * 32;
    int d0 = blockIdx.y * 32;
    int tx = threadIdx.x, ty = threadIdx.y;  // (32, 8)
    const float* src = nf + (size_t)b * NN * DD;
    #pragma unroll
    for (int j = 0; j < 4; j++)
        tile[ty + j * 8][tx] = src[(size_t)(n0 + ty + j * 8) * DD + d0 + tx];
    __syncthreads();
    __half* dst = g_bh + (size_t)b * DD * NN;
    #pragma unroll
    for (int j = 0; j < 4; j++)
        dst[(size_t)(d0 + ty + j * 8) * NN + n0 + tx] = __float2half(tile[tx][ty + j * 8]);
    if (ty == 0) {
        float s = 0.f;
        #pragma unroll
        for (int i = 0; i < 32; i++) s += tile[i][tx];
        g_nfs_part[((size_t)b * NSPL + (n0 >> 5)) * DD + d0 + tx] = s;
    }
}

__global__ void nfs_final_kernel(float* __restrict__ out) {
    int b = blockIdx.x, d = threadIdx.x;
    float s = 0.f;
    #pragma unroll
    for (int t = 0; t < NSPL; t++) s += g_nfs_part[((size_t)b * NSPL + t) * DD + d];
    out[OFF_NFS + (size_t)b * DD + d] = s;
}

// ---------------------------------------------------------------------------
// 3) Per-(b,h) row reductions; also emits fp16 copy of pred_inc
// ---------------------------------------------------------------------------
__global__ __launch_bounds__(256, 5)
void row_kernel(const float* __restrict__ pred_inc,
                const float* __restrict__ track_pt,
                const float* __restrict__ track_eta,
                const float* __restrict__ track_phi,
                const int*   __restrict__ is_track,
                float* __restrict__ out) {
    int pr = blockIdx.x * (blockDim.x >> 5) + (threadIdx.x >> 5);  // row-pair
    if (pr >= (BB * HH) / 2) return;
    int lane = threadIdx.x & 31;
    int row0 = pr * 2;
    int b = row0 / HH;

    const float4* p4 = (const float4*)(pred_inc + (size_t)row0 * NN);
    const float4* q4 = (const float4*)(pred_inc + (size_t)(row0 + 1) * NN);
    const float4* w4 = (const float4*)(g_w    + b * NN);
    const float4* e4 = (const float4*)(g_weta + b * NN);
    const float4* s4 = (const float4*)(g_wsin + b * NN);
    const float4* c4 = (const float4*)(g_wcos + b * NN);
    const float4* m4 = (const float4*)(g_wem  + b * NN);
    uint2* hp = (uint2*)(g_ah + (size_t)row0 * NN);
    uint2* hq = (uint2*)(g_ah + (size_t)(row0 + 1) * NN);

    float a0 = 0.f, a1 = 0.f, a2 = 0.f, a3 = 0.f, a4 = 0.f;
    float b0 = 0.f, b1 = 0.f, b2 = 0.f, b3 = 0.f, b4 = 0.f;
    #pragma unroll 2
    for (int i = lane; i < NN / 4; i += 32) {
        float4 p = p4[i];
        float4 q = q4[i];
        // fp16 copies for the GEMM
        {
            __half2 h0 = __floats2half2_rn(p.x, p.y);
            __half2 h1 = __floats2half2_rn(p.z, p.w);
            uint2 st;
            st.x = *(uint32_t*)&h0; st.y = *(uint32_t*)&h1;
            hp[i] = st;
            __half2 g0 = __floats2half2_rn(q.x, q.y);
            __half2 g1 = __floats2half2_rn(q.z, q.w);
            st.x = *(uint32_t*)&g0; st.y = *(uint32_t*)&g1;
            hq[i] = st;
        }
        float4 w = w4[i];
        a0 = fmaf(p.x, w.x, a0); a0 = fmaf(p.y, w.y, a0);
        a0 = fmaf(p.z, w.z, a0); a0 = fmaf(p.w, w.w, a0);
        b0 = fmaf(q.x, w.x, b0); b0 = fmaf(q.y, w.y, b0);
        b0 = fmaf(q.z, w.z, b0); b0 = fmaf(q.w, w.w, b0);
        float4 e = e4[i];
        a1 = fmaf(p.x, e.x, a1); a1 = fmaf(p.y, e.y, a1);
        a1 = fmaf(p.z, e.z, a1); a1 = fmaf(p.w, e.w, a1);
        b1 = fmaf(q.x, e.x, b1); b1 = fmaf(q.y, e.y, b1);
        b1 = fmaf(q.z, e.z, b1); b1 = fmaf(q.w, e.w, b1);
        float4 s = s4[i];
        a2 = fmaf(p.x, s.x, a2); a2 = fmaf(p.y, s.y, a2);
        a2 = fmaf(p.z, s.z, a2); a2 = fmaf(p.w, s.w, a2);
        b2 = fmaf(q.x, s.x, b2); b2 = fmaf(q.y, s.y, b2);
        b2 = fmaf(q.z, s.z, b2); b2 = fmaf(q.w, s.w, b2);
        float4 c = c4[i];
        a3 = fmaf(p.x, c.x, a3); a3 = fmaf(p.y, c.y, a3);
        a3 = fmaf(p.z, c.z, a3); a3 = fmaf(p.w, c.w, a3);
        b3 = fmaf(q.x, c.x, b3); b3 = fmaf(q.y, c.y, b3);
        b3 = fmaf(q.z, c.z, b3); b3 = fmaf(q.w, c.w, b3);
        float4 m = m4[i];
        a4 = fmaf(p.x, m.x, a4); a4 = fmaf(p.y, m.y, a4);
        a4 = fmaf(p.z, m.z, a4); a4 = fmaf(p.w, m.w, a4);
        b4 = fmaf(q.x, m.x, b4); b4 = fmaf(q.y, m.y, b4);
        b4 = fmaf(q.z, m.z, b4); b4 = fmaf(q.w, m.w, b4);
    }
    #pragma unroll
    for (int o = 16; o > 0; o >>= 1) {
        a0 += __shfl_xor_sync(0xFFFFFFFFu, a0, o);
        a1 += __shfl_xor_sync(0xFFFFFFFFu, a1, o);
        a2 += __shfl_xor_sync(0xFFFFFFFFu, a2, o);
        a3 += __shfl_xor_sync(0xFFFFFFFFu, a3, o);
        a4 += __shfl_xor_sync(0xFFFFFFFFu, a4, o);
        b0 += __shfl_xor_sync(0xFFFFFFFFu, b0, o);
        b1 += __shfl_xor_sync(0xFFFFFFFFu, b1, o);
        b2 += __shfl_xor_sync(0xFFFFFFFFu, b2, o);
        b3 += __shfl_xor_sync(0xFFFFFFFFu, b3, o);
        b4 += __shfl_xor_sync(0xFFFFFFFFu, b4, o);
    }
    if (lane == 0) {
        #pragma unroll
        for (int rr = 0; rr < 2; rr++) {
            int   row = row0 + rr;
            int   h   = row % HH;
            float s0  = rr ? b0 : a0;
            float s1  = rr ? b1 : a1;
            float s2  = rr ? b2 : a2;
            float s3  = rr ? b3 : a3;
            float s4v = rr ? b4 : a4;

            float inv = 1.f / (s0 + EPSV);
            bool  pc  = (h < NN) && (is_track[b * NN + h] != 0);
            float nm  = pc ? 0.f : 1.f;

            float ke  = log1pf(fmaxf(s0, 0.f));
            float eta = s1 * inv * (1.f / 3.0f);
            float ph  = atan2f(s2 * inv, s3 * inv);
            float em  = s4v * inv;

            long long r3 = (long long)row * 3;
            float cpt = 0.f, ceta = 0.f, cphi = 0.f;
            if (pc) {
                cpt  = track_pt [b * NN + h];
                ceta = track_eta[b * NN + h];
                cphi = track_phi[b * NN + h];
            }
            out[OFF_CH + r3 + 0] = cpt;
            out[OFF_CH + r3 + 1] = ceta;
            out[OFF_CH + r3 + 2] = cphi;
            out[OFF_NEUT + r3 + 0] = ke  * nm;
            out[OFF_NEUT + r3 + 1] = eta * nm;
            out[OFF_NEUT + r3 + 2] = ph  * nm;
            out[OFF_PC + row] = pc ? 1.f : 0.f;
            out[OFF_EM + row] = em;
        }
    }
}

// ---------------------------------------------------------------------------
// 4) fp16 mma.sync GEMM: block 128x128, BK=32 halfs, 128 threads (4 warps
//    2x2, warp tile 64x64). No cvt in inner loop; B pre-transposed k-major.
// ---------------------------------------------------------------------------
#define BM 128
#define BN 128
#define BKH 32
#define KPAD 40                     // halfs per smem row (80 B)
#define A_H (BM * KPAD)             // 5120 halfs
#define B_H (BN * KPAD)
#define STG_H (A_H + B_H)           // 10240 halfs = 20480 B

__global__ __launch_bounds__(128)
void gemm_mma_kernel(float* __restrict__ C) {   // [B][H][D]
    __shared__ __align__(16) __half smem[2 * STG_H];

    int tid  = threadIdx.x;
    int wid  = tid >> 5;
    int lane = tid & 31;
    int gid  = lane >> 2;       // 0..7
    int tig  = lane & 3;        // 0..3
    int warp_m = wid & 1;
    int warp_n = wid >> 1;

    int b  = blockIdx.z;
    int m0 = blockIdx.y * BM;
    int n0 = blockIdx.x * BN;

    const __half* Ah = g_ah + ((size_t)b * HH + m0) * NN;
    const __half* Bh = g_bh + ((size_t)b * DD + n0) * NN;

    int lr = tid >> 2;   // 0..31 (+32 per pass)
    int lj = tid & 3;    // 16B chunk (8 halfs)

    float acc[4][8][4];
    #pragma unroll
    for (int i = 0; i < 4; i++)
        #pragma unroll
        for (int j = 0; j < 8; j++)
            #pragma unroll
            for (int k = 0; k < 4; k++) acc[i][j][k] = 0.f;

    auto load_tile = [&](int t, int s) {
        __half* as = smem + s * STG_H;
        __half* bs = as + A_H;
        int k0 = t * BKH;
        #pragma unroll
        for (int i = 0; i < 4; i++) {
            int r = lr + i * 32;
            cp16(smem_u32(as + r * KPAD + lj * 8), Ah + (size_t)r * NN + k0 + lj * 8);
            cp16(smem_u32(bs + r * KPAD + lj * 8), Bh + (size_t)r * NN + k0 + lj * 8);
        }
        cp_commit();
    };

    load_tile(0, 0);

    const int NT = NN / BKH;  // 32
    for (int t = 0; t < NT; t++) {
        if (t + 1 < NT) {
            load_tile(t + 1, (t + 1) & 1);
            cp_wait<1>();
        } else {
            cp_wait<0>();
        }
        __syncthreads();

        const __half* as = smem + (t & 1) * STG_H;
        const __half* bs = as + A_H;

        #pragma unroll
        for (int kk = 0; kk < BKH; kk += 16) {
            uint32_t bf[8][2];
            #pragma unroll
            for (int nf = 0; nf < 8; nf++) {
                int n = warp_n * 64 + nf * 8 + gid;
                bf[nf][0] = *(const uint32_t*)(bs + (size_t)n * KPAD + kk + 2 * tig);
                bf[nf][1] = *(const uint32_t*)(bs + (size_t)n * KPAD + kk + 2 * tig + 8);
            }
            #pragma unroll
            for (int mf = 0; mf < 4; mf++) {
                int m = warp_m * 64 + mf * 16 + gid;
                uint32_t af[4];
                af[0] = *(const uint32_t*)(as + (size_t)m * KPAD + kk + 2 * tig);
                af[1] = *(const uint32_t*)(as + (size_t)(m + 8) * KPAD + kk + 2 * tig);
                af[2] = *(const uint32_t*)(as + (size_t)m * KPAD + kk + 2 * tig + 8);
                af[3] = *(const uint32_t*)(as + (size_t)(m + 8) * KPAD + kk + 2 * tig + 8);
                #pragma unroll
                for (int nf = 0; nf < 8; nf++)
                    mma_f16(acc[mf][nf], af, bf[nf]);
            }
        }
        __syncthreads();
    }

    // Epilogue
    float* Cb = C + ((size_t)b * HH + m0) * DD + n0;
    #pragma unroll
    for (int mf = 0; mf < 4; mf++) {
        int r0 = warp_m * 64 + mf * 16 + gid;
        #pragma unroll
        for (int nf = 0; nf < 8; nf++) {
            int cc = warp_n * 64 + nf * 8 + tig * 2;
            *(float2*)(Cb + (size_t)r0 * DD + cc) =
                make_float2(acc[mf][nf][0], acc[mf][nf][1]);
            *(float2*)(Cb + (size_t)(r0 + 8) * DD + cc) =
                make_float2(acc[mf][nf][2], acc[mf][nf][3]);
        }
    }
}

// ---------------------------------------------------------------------------
extern "C" void kernel_launch(void* const* d_in, const int* in_sizes, int n_in,
                              void* d_out, int out_size) {
    const float* pred_inc  = (const float*)d_in[0];
    const float* node_feat = (const float*)d_in[1];
    const float* e_raw     = (const float*)d_in[2];
    const float* eta_raw   = (const float*)d_in[3];
    const float* phi       = (const float*)d_in[4];
    const float* em_frac   = (const float*)d_in[5];
    const float* track_pt  = (const float*)d_in[6];
    const float* track_eta = (const float*)d_in[7];
    const float* track_phi = (const float*)d_in[8];
    const int*   is_track  = (const int*)d_in[9];
    const int*   is_topo   = (const int*)d_in[10];
    float* out = (float*)d_out;

    prep_kernel<<<(BB * NN + 255) / 256, 256>>>(e_raw, eta_raw, phi, em_frac, is_topo);

    {
        dim3 grid(NN / 32, DD / 32, BB);
        transpose_kernel<<<grid, dim3(32, 8)>>>(node_feat);
    }
    nfs_final_kernel<<<BB, DD>>>(out);

    {
        int pairs = (BB * HH) / 2;
        int warps_per_blk = 8;
        int blocks = (pairs + warps_per_blk - 1) / warps_per_blk;
        row_kernel<<<blocks, warps_per_blk * 32>>>(pred_inc, track_pt, track_eta,
                                                   track_phi, is_track, out);
    }

    {
        dim3 grid(DD / BN, HH / BM, BB);
        gemm_mma_kernel<<<grid, 128>>>(out + OFF_MM);
    }
}

// round 8
// speedup vs baseline: 3.0428x; 1.0175x over previous
#include <cuda_runtime.h>
#include <cuda_fp16.h>
#include <math.h>
#include <stdint.h>

// Problem shape (fixed by the dataset)
#define BB 16
#define NN 1024
#define HH 1280
#define DD 256
#define EPSV 1e-8f

// Output segment offsets (elements), tuple flattened in order, float32
#define OFF_CH   0LL
#define OFF_NEUT (OFF_CH   + (long long)BB*HH*3)
#define OFF_PC   (OFF_NEUT + (long long)BB*HH*3)
#define OFF_EM   (OFF_PC   + (long long)BB*HH)
#define OFF_MM   (OFF_EM   + (long long)BB*HH)
#define OFF_NFS  (OFF_MM   + (long long)BB*HH*DD)

// Device scratch
__device__ float  g_w   [BB*NN];
__device__ float  g_weta[BB*NN];
__device__ float  g_wsin[BB*NN];
__device__ float  g_wcos[BB*NN];
__device__ float  g_wem [BB*NN];
__device__ __half g_ah[(size_t)BB*HH*NN];   // pred_inc fp16 [b][h][n]
__device__ __half g_bh[(size_t)BB*DD*NN];   // node_feat fp16 [b][d][n]
#define NSPL 32
__device__ float  g_nfs_part[BB*NSPL*DD];

// ---------------------------------------------------------------------------
// PTX helpers (baseline PTX only)
// ---------------------------------------------------------------------------
__device__ __forceinline__ uint32_t smem_u32(const void* p) {
    return (uint32_t)__cvta_generic_to_shared(p);
}
__device__ __forceinline__ void cp16(uint32_t dst, const void* src) {
    asm volatile("cp.async.cg.shared.global [%0], [%1], 16;"
                 :: "r"(dst), "l"(src) : "memory");
}
__device__ __forceinline__ void cp_commit() {
    asm volatile("cp.async.commit_group;" ::: "memory");
}
template <int N>
__device__ __forceinline__ void cp_wait() {
    asm volatile("cp.async.wait_group %0;" :: "n"(N) : "memory");
}
__device__ __forceinline__ void mma_f16(float* c, const uint32_t* a, const uint32_t* b) {
    asm volatile(
        "mma.sync.aligned.m16n8k16.row.col.f32.f16.f16.f32 "
        "{%0,%1,%2,%3}, {%4,%5,%6,%7}, {%8,%9}, {%0,%1,%2,%3};"
        : "+f"(c[0]), "+f"(c[1]), "+f"(c[2]), "+f"(c[3])
        : "r"(a[0]), "r"(a[1]), "r"(a[2]), "r"(a[3]), "r"(b[0]), "r"(b[1]));
}
#define LDSM_X4(r0, r1, r2, r3, addr) \
    asm volatile("ldmatrix.sync.aligned.m8n8.x4.shared.b16 {%0,%1,%2,%3}, [%4];" \
                 : "=r"(r0), "=r"(r1), "=r"(r2), "=r"(r3) : "r"(addr))

// ---------------------------------------------------------------------------
// 1) Precompute w = e_raw*is_topo and its products (fp32)
// ---------------------------------------------------------------------------
__global__ void prep_kernel(const float* __restrict__ e_raw,
                            const float* __restrict__ eta_raw,
                            const float* __restrict__ phi,
                            const float* __restrict__ em_frac,
                            const int*   __restrict__ is_topo) {
    int i = blockIdx.x * blockDim.x + threadIdx.x;
    if (i >= BB * NN) return;
    float w = e_raw[i] * (float)is_topo[i];
    float s, c;
    sincosf(phi[i], &s, &c);
    g_w[i]    = w;
    g_weta[i] = w * eta_raw[i];
    g_wsin[i] = w * s;
    g_wcos[i] = w * c;
    g_wem[i]  = w * em_frac[i];
}

// ---------------------------------------------------------------------------
// 2) Transpose node_feat [b,n,d] -> g_bh fp16 [b,d,n]; fused nfs partials
// ---------------------------------------------------------------------------
__global__ void transpose_kernel(const float* __restrict__ nf) {
    __shared__ float tile[32][33];
    int b  = blockIdx.z;
    int n0 = blockIdx.x * 32;
    int d0 = blockIdx.y * 32;
    int tx = threadIdx.x, ty = threadIdx.y;  // (32, 8)
    const float* src = nf + (size_t)b * NN * DD;
    #pragma unroll
    for (int j = 0; j < 4; j++)
        tile[ty + j * 8][tx] = src[(size_t)(n0 + ty + j * 8) * DD + d0 + tx];
    __syncthreads();
    __half* dst = g_bh + (size_t)b * DD * NN;
    #pragma unroll
    for (int j = 0; j < 4; j++)
        dst[(size_t)(d0 + ty + j * 8) * NN + n0 + tx] = __float2half(tile[tx][ty + j * 8]);
    if (ty == 0) {
        float s = 0.f;
        #pragma unroll
        for (int i = 0; i < 32; i++) s += tile[i][tx];
        g_nfs_part[((size_t)b * NSPL + (n0 >> 5)) * DD + d0 + tx] = s;
    }
}

__global__ void nfs_final_kernel(float* __restrict__ out) {
    int b = blockIdx.x, d = threadIdx.x;
    float s = 0.f;
    #pragma unroll
    for (int t = 0; t < NSPL; t++) s += g_nfs_part[((size_t)b * NSPL + t) * DD + d];
    out[OFF_NFS + (size_t)b * DD + d] = s;
}

// ---------------------------------------------------------------------------
// 3) Per-(b,h) row reductions (fp32 FFMA — precision-critical); also emits
//    fp16 copy of pred_inc for the GEMM. Two rows per warp share weight loads.
// ---------------------------------------------------------------------------
__global__ __launch_bounds__(256, 5)
void row_kernel(const float* __restrict__ pred_inc,
                const float* __restrict__ track_pt,
                const float* __restrict__ track_eta,
                const float* __restrict__ track_phi,
                const int*   __restrict__ is_track,
                float* __restrict__ out) {
    int pr = blockIdx.x * (blockDim.x >> 5) + (threadIdx.x >> 5);  // row-pair
    if (pr >= (BB * HH) / 2) return;
    int lane = threadIdx.x & 31;
    int row0 = pr * 2;
    int b = row0 / HH;

    const float4* p4 = (const float4*)(pred_inc + (size_t)row0 * NN);
    const float4* q4 = (const float4*)(pred_inc + (size_t)(row0 + 1) * NN);
    const float4* w4 = (const float4*)(g_w    + b * NN);
    const float4* e4 = (const float4*)(g_weta + b * NN);
    const float4* s4 = (const float4*)(g_wsin + b * NN);
    const float4* c4 = (const float4*)(g_wcos + b * NN);
    const float4* m4 = (const float4*)(g_wem  + b * NN);
    uint2* hp = (uint2*)(g_ah + (size_t)row0 * NN);
    uint2* hq = (uint2*)(g_ah + (size_t)(row0 + 1) * NN);

    float a0 = 0.f, a1 = 0.f, a2 = 0.f, a3 = 0.f, a4 = 0.f;
    float b0 = 0.f, b1 = 0.f, b2 = 0.f, b3 = 0.f, b4 = 0.f;
    #pragma unroll 2
    for (int i = lane; i < NN / 4; i += 32) {
        float4 p = p4[i];
        float4 q = q4[i];
        {
            __half2 h0 = __floats2half2_rn(p.x, p.y);
            __half2 h1 = __floats2half2_rn(p.z, p.w);
            uint2 st;
            st.x = *(uint32_t*)&h0; st.y = *(uint32_t*)&h1;
            hp[i] = st;
            __half2 g0 = __floats2half2_rn(q.x, q.y);
            __half2 g1 = __floats2half2_rn(q.z, q.w);
            st.x = *(uint32_t*)&g0; st.y = *(uint32_t*)&g1;
            hq[i] = st;
        }
        float4 w = w4[i];
        a0 = fmaf(p.x, w.x, a0); a0 = fmaf(p.y, w.y, a0);
        a0 = fmaf(p.z, w.z, a0); a0 = fmaf(p.w, w.w, a0);
        b0 = fmaf(q.x, w.x, b0); b0 = fmaf(q.y, w.y, b0);
        b0 = fmaf(q.z, w.z, b0); b0 = fmaf(q.w, w.w, b0);
        float4 e = e4[i];
        a1 = fmaf(p.x, e.x, a1); a1 = fmaf(p.y, e.y, a1);
        a1 = fmaf(p.z, e.z, a1); a1 = fmaf(p.w, e.w, a1);
        b1 = fmaf(q.x, e.x, b1); b1 = fmaf(q.y, e.y, b1);
        b1 = fmaf(q.z, e.z, b1); b1 = fmaf(q.w, e.w, b1);
        float4 s = s4[i];
        a2 = fmaf(p.x, s.x, a2); a2 = fmaf(p.y, s.y, a2);
        a2 = fmaf(p.z, s.z, a2); a2 = fmaf(p.w, s.w, a2);
        b2 = fmaf(q.x, s.x, b2); b2 = fmaf(q.y, s.y, b2);
        b2 = fmaf(q.z, s.z, b2); b2 = fmaf(q.w, s.w, b2);
        float4 c = c4[i];
        a3 = fmaf(p.x, c.x, a3); a3 = fmaf(p.y, c.y, a3);
        a3 = fmaf(p.z, c.z, a3); a3 = fmaf(p.w, c.w, a3);
        b3 = fmaf(q.x, c.x, b3); b3 = fmaf(q.y, c.y, b3);
        b3 = fmaf(q.z, c.z, b3); b3 = fmaf(q.w, c.w, b3);
        float4 m = m4[i];
        a4 = fmaf(p.x, m.x, a4); a4 = fmaf(p.y, m.y, a4);
        a4 = fmaf(p.z, m.z, a4); a4 = fmaf(p.w, m.w, a4);
        b4 = fmaf(q.x, m.x, b4); b4 = fmaf(q.y, m.y, b4);
        b4 = fmaf(q.z, m.z, b4); b4 = fmaf(q.w, m.w, b4);
    }
    #pragma unroll
    for (int o = 16; o > 0; o >>= 1) {
        a0 += __shfl_xor_sync(0xFFFFFFFFu, a0, o);
        a1 += __shfl_xor_sync(0xFFFFFFFFu, a1, o);
        a2 += __shfl_xor_sync(0xFFFFFFFFu, a2, o);
        a3 += __shfl_xor_sync(0xFFFFFFFFu, a3, o);
        a4 += __shfl_xor_sync(0xFFFFFFFFu, a4, o);
        b0 += __shfl_xor_sync(0xFFFFFFFFu, b0, o);
        b1 += __shfl_xor_sync(0xFFFFFFFFu, b1, o);
        b2 += __shfl_xor_sync(0xFFFFFFFFu, b2, o);
        b3 += __shfl_xor_sync(0xFFFFFFFFu, b3, o);
        b4 += __shfl_xor_sync(0xFFFFFFFFu, b4, o);
    }
    if (lane == 0) {
        #pragma unroll
        for (int rr = 0; rr < 2; rr++) {
            int   row = row0 + rr;
            int   h   = row % HH;
            float s0  = rr ? b0 : a0;
            float s1  = rr ? b1 : a1;
            float s2  = rr ? b2 : a2;
            float s3  = rr ? b3 : a3;
            float s4v = rr ? b4 : a4;

            float inv = 1.f / (s0 + EPSV);
            bool  pc  = (h < NN) && (is_track[b * NN + h] != 0);
            float nm  = pc ? 0.f : 1.f;

            float ke  = log1pf(fmaxf(s0, 0.f));
            float eta = s1 * inv * (1.f / 3.0f);
            float ph  = atan2f(s2 * inv, s3 * inv);
            float em  = s4v * inv;

            long long r3 = (long long)row * 3;
            float cpt = 0.f, ceta = 0.f, cphi = 0.f;
            if (pc) {
                cpt  = track_pt [b * NN + h];
                ceta = track_eta[b * NN + h];
                cphi = track_phi[b * NN + h];
            }
            out[OFF_CH + r3 + 0] = cpt;
            out[OFF_CH + r3 + 1] = ceta;
            out[OFF_CH + r3 + 2] = cphi;
            out[OFF_NEUT + r3 + 0] = ke  * nm;
            out[OFF_NEUT + r3 + 1] = eta * nm;
            out[OFF_NEUT + r3 + 2] = ph  * nm;
            out[OFF_PC + row] = pc ? 1.f : 0.f;
            out[OFF_EM + row] = em;
        }
    }
}

// ---------------------------------------------------------------------------
// 4) fp16 mma GEMM with ldmatrix: block 128x128, BK=32 halfs, 128 threads
//    (4 warps, 2x2, warp tile 64x64). 2-stage cp.async.
// ---------------------------------------------------------------------------
#define BM 128
#define BN 128
#define BKH 32
#define KPAD 40
#define A_H (BM * KPAD)
#define B_H (BN * KPAD)
#define STG_H (A_H + B_H)

__global__ __launch_bounds__(128)
void gemm_mma_kernel(float* __restrict__ C) {   // [B][H][D]
    __shared__ __align__(16) __half smem[2 * STG_H];

    int tid  = threadIdx.x;
    int wid  = tid >> 5;
    int lane = tid & 31;
    int gid  = lane >> 2;
    int tig  = lane & 3;
    int warp_m = wid & 1;
    int warp_n = wid >> 1;
    int q  = lane >> 3;   // ldmatrix quadrant
    int rr = lane & 7;

    int b  = blockIdx.z;
    int m0 = blockIdx.y * BM;
    int n0 = blockIdx.x * BN;

    const __half* Ah = g_ah + ((size_t)b * HH + m0) * NN;
    const __half* Bh = g_bh + ((size_t)b * DD + n0) * NN;

    int lr = tid >> 2;
    int lj = tid & 3;

    uint32_t a_off = (uint32_t)(((warp_m * 64 + (q & 1) * 8 + rr) * KPAD + (q >> 1) * 8) * 2);
    uint32_t b_off = (uint32_t)(((warp_n * 64 + (q >> 1) * 8 + rr) * KPAD + (q & 1) * 8) * 2);

    float acc[4][8][4];
    #pragma unroll
    for (int i = 0; i < 4; i++)
        #pragma unroll
        for (int j = 0; j < 8; j++)
            #pragma unroll
            for (int k = 0; k < 4; k++) acc[i][j][k] = 0.f;

    auto load_tile = [&](int t, int s) {
        __half* asx = smem + s * STG_H;
        __half* bsx = asx + A_H;
        int k0 = t * BKH;
        #pragma unroll
        for (int i = 0; i < 4; i++) {
            int r = lr + i * 32;
            cp16(smem_u32(asx + r * KPAD + lj * 8), Ah + (size_t)r * NN + k0 + lj * 8);
            cp16(smem_u32(bsx + r * KPAD + lj * 8), Bh + (size_t)r * NN + k0 + lj * 8);
        }
        cp_commit();
    };

    load_tile(0, 0);

    const int NT = NN / BKH;  // 32
    for (int t = 0; t < NT; t++) {
        if (t + 1 < NT) {
            load_tile(t + 1, (t + 1) & 1);
            cp_wait<1>();
        } else {
            cp_wait<0>();
        }
        __syncthreads();

        uint32_t as_u = smem_u32(smem + (t & 1) * STG_H);
        uint32_t bs_u = as_u + A_H * 2;

        #pragma unroll
        for (int kk = 0; kk < BKH; kk += 16) {
            uint32_t bf[8][2];
            #pragma unroll
            for (int nf2 = 0; nf2 < 4; nf2++) {
                uint32_t r0, r1, r2, r3;
                LDSM_X4(r0, r1, r2, r3,
                        bs_u + b_off + (uint32_t)((nf2 * 16 * KPAD + kk) * 2));
                bf[2 * nf2][0]     = r0;
                bf[2 * nf2][1]     = r1;
                bf[2 * nf2 + 1][0] = r2;
                bf[2 * nf2 + 1][1] = r3;
            }
            #pragma unroll
            for (int mf = 0; mf < 4; mf++) {
                uint32_t af[4];
                LDSM_X4(af[0], af[1], af[2], af[3],
                        as_u + a_off + (uint32_t)((mf * 16 * KPAD + kk) * 2));
                #pragma unroll
                for (int nf = 0; nf < 8; nf++)
                    mma_f16(acc[mf][nf], af, bf[nf]);
            }
        }
        __syncthreads();
    }

    // Epilogue
    float* Cb = C + ((size_t)b * HH + m0) * DD + n0;
    #pragma unroll
    for (int mf = 0; mf < 4; mf++) {
        int r0 = warp_m * 64 + mf * 16 + gid;
        #pragma unroll
        for (int nf = 0; nf < 8; nf++) {
            int cc = warp_n * 64 + nf * 8 + tig * 2;
            *(float2*)(Cb + (size_t)r0 * DD + cc) =
                make_float2(acc[mf][nf][0], acc[mf][nf][1]);
            *(float2*)(Cb + (size_t)(r0 + 8) * DD + cc) =
                make_float2(acc[mf][nf][2], acc[mf][nf][3]);
        }
    }
}

// ---------------------------------------------------------------------------
extern "C" void kernel_launch(void* const* d_in, const int* in_sizes, int n_in,
                              void* d_out, int out_size) {
    const float* pred_inc  = (const float*)d_in[0];
    const float* node_feat = (const float*)d_in[1];
    const float* e_raw     = (const float*)d_in[2];
    const float* eta_raw   = (const float*)d_in[3];
    const float* phi       = (const float*)d_in[4];
    const float* em_frac   = (const float*)d_in[5];
    const float* track_pt  = (const float*)d_in[6];
    const float* track_eta = (const float*)d_in[7];
    const float* track_phi = (const float*)d_in[8];
    const int*   is_track  = (const int*)d_in[9];
    const int*   is_topo   = (const int*)d_in[10];
    float* out = (float*)d_out;

    prep_kernel<<<(BB * NN + 255) / 256, 256>>>(e_raw, eta_raw, phi, em_frac, is_topo);

    {
        dim3 grid(NN / 32, DD / 32, BB);
        transpose_kernel<<<grid, dim3(32, 8)>>>(node_feat);
    }
    nfs_final_kernel<<<BB, DD>>>(out);

    {
        int pairs = (BB * HH) / 2;
        int warps_per_blk = 8;
        int blocks = (pairs + warps_per_blk - 1) / warps_per_blk;
        row_kernel<<<blocks, warps_per_blk * 32>>>(pred_inc, track_pt, track_eta,
                                                   track_phi, is_track, out);
    }

    {
        dim3 grid(DD / BN, HH / BM, BB);
        gemm_mma_kernel<<<grid, 128>>>(out + OFF_MM);
    }
}

// round 9
// speedup vs baseline: 3.7980x; 1.2482x over previous
#include <cuda_runtime.h>
#include <cuda_fp16.h>
#include <math.h>
#include <stdint.h>

// Problem shape (fixed by the dataset)
#define BB 16
#define NN 1024
#define HH 1280
#define DD 256
#define EPSV 1e-8f

// Output segment offsets (elements), tuple flattened in order, float32
#define OFF_CH   0LL
#define OFF_NEUT (OFF_CH   + (long long)BB*HH*3)
#define OFF_PC   (OFF_NEUT + (long long)BB*HH*3)
#define OFF_EM   (OFF_PC   + (long long)BB*HH)
#define OFF_MM   (OFF_EM   + (long long)BB*HH)
#define OFF_NFS  (OFF_MM   + (long long)BB*HH*DD)

// Device scratch
__device__ float  g_w   [BB*NN];
__device__ float  g_weta[BB*NN];
__device__ float  g_wsin[BB*NN];
__device__ float  g_wcos[BB*NN];
__device__ float  g_wem [BB*NN];
__device__ __half g_ah[(size_t)BB*HH*NN];   // pred_inc fp16 [b][h][n]
__device__ __half g_bh[(size_t)BB*DD*NN];   // node_feat fp16 [b][d][n]
#define NSPL 32
__device__ float  g_nfs_part[BB*NSPL*DD];

// ---------------------------------------------------------------------------
// PTX helpers (baseline PTX only)
// ---------------------------------------------------------------------------
__device__ __forceinline__ uint32_t smem_u32(const void* p) {
    return (uint32_t)__cvta_generic_to_shared(p);
}
__device__ __forceinline__ void cp16(uint32_t dst, const void* src) {
    asm volatile("cp.async.cg.shared.global [%0], [%1], 16;"
                 :: "r"(dst), "l"(src) : "memory");
}
__device__ __forceinline__ void cp_commit() {
    asm volatile("cp.async.commit_group;" ::: "memory");
}
template <int N>
__device__ __forceinline__ void cp_wait() {
    asm volatile("cp.async.wait_group %0;" :: "n"(N) : "memory");
}
__device__ __forceinline__ void mma_f16(float* c, const uint32_t* a, const uint32_t* b) {
    asm volatile(
        "mma.sync.aligned.m16n8k16.row.col.f32.f16.f16.f32 "
        "{%0,%1,%2,%3}, {%4,%5,%6,%7}, {%8,%9}, {%0,%1,%2,%3};"
        : "+f"(c[0]), "+f"(c[1]), "+f"(c[2]), "+f"(c[3])
        : "r"(a[0]), "r"(a[1]), "r"(a[2]), "r"(a[3]), "r"(b[0]), "r"(b[1]));
}
#define LDSM_X4(r0, r1, r2, r3, addr) \
    asm volatile("ldmatrix.sync.aligned.m8n8.x4.shared.b16 {%0,%1,%2,%3}, [%4];" \
                 : "=r"(r0), "=r"(r1), "=r"(r2), "=r"(r3) : "r"(addr))

// ---------------------------------------------------------------------------
// 1) Precompute w = e_raw*is_topo and its products (fp32)
// ---------------------------------------------------------------------------
__global__ void prep_kernel(const float* __restrict__ e_raw,
                            const float* __restrict__ eta_raw,
                            const float* __restrict__ phi,
                            const float* __restrict__ em_frac,
                            const int*   __restrict__ is_topo) {
    int i = blockIdx.x * blockDim.x + threadIdx.x;
    if (i >= BB * NN) return;
    float w = e_raw[i] * (float)is_topo[i];
    float s, c;
    sincosf(phi[i], &s, &c);
    g_w[i]    = w;
    g_weta[i] = w * eta_raw[i];
    g_wsin[i] = w * s;
    g_wcos[i] = w * c;
    g_wem[i]  = w * em_frac[i];
}

// ---------------------------------------------------------------------------
// 2) Transpose node_feat [b,n,d] -> g_bh fp16 [b,d,n]; fused nfs partials
// ---------------------------------------------------------------------------
__global__ void transpose_kernel(const float* __restrict__ nf) {
    __shared__ float tile[32][33];
    int b  = blockIdx.z;
    int n0 = blockIdx.x * 32;
    int d0 = blockIdx.y * 32;
    int tx = threadIdx.x, ty = threadIdx.y;  // (32, 8)
    const float* src = nf + (size_t)b * NN * DD;
    #pragma unroll
    for (int j = 0; j < 4; j++)
        tile[ty + j * 8][tx] = src[(size_t)(n0 + ty + j * 8) * DD + d0 + tx];
    __syncthreads();
    __half* dst = g_bh + (size_t)b * DD * NN;
    #pragma unroll
    for (int j = 0; j < 4; j++)
        dst[(size_t)(d0 + ty + j * 8) * NN + n0 + tx] = __float2half(tile[tx][ty + j * 8]);
    if (ty == 0) {
        float s = 0.f;
        #pragma unroll
        for (int i = 0; i < 32; i++) s += tile[i][tx];
        g_nfs_part[((size_t)b * NSPL + (n0 >> 5)) * DD + d0 + tx] = s;
    }
}

__global__ void nfs_final_kernel(float* __restrict__ out) {
    int b = blockIdx.x, d = threadIdx.x;
    float s = 0.f;
    #pragma unroll
    for (int t = 0; t < NSPL; t++) s += g_nfs_part[((size_t)b * NSPL + t) * DD + d];
    out[OFF_NFS + (size_t)b * DD + d] = s;
}

// ---------------------------------------------------------------------------
// 3) Row reductions (fp32 FFMA); weights staged in SMEM; emits fp16 pred_inc.
//    Block: 256 threads = 8 warps = 16 rows of one batch. 20 KB smem weights.
// ---------------------------------------------------------------------------
__global__ __launch_bounds__(256, 5)
void row_kernel(const float* __restrict__ pred_inc,
                const float* __restrict__ track_pt,
                const float* __restrict__ track_eta,
                const float* __restrict__ track_phi,
                const int*   __restrict__ is_track,
                float* __restrict__ out) {
    __shared__ float sw[5][NN];

    int tid  = threadIdx.x;
    int lane = tid & 31;
    int wid  = tid >> 5;
    int b    = blockIdx.y;
    int row0 = b * HH + blockIdx.x * 16 + wid * 2;

    // Stage weights for this batch (each thread: 5 float4 loads)
    {
        float4 v;
        v = ((const float4*)(g_w    + b * NN))[tid]; *(float4*)&sw[0][tid * 4] = v;
        v = ((const float4*)(g_weta + b * NN))[tid]; *(float4*)&sw[1][tid * 4] = v;
        v = ((const float4*)(g_wsin + b * NN))[tid]; *(float4*)&sw[2][tid * 4] = v;
        v = ((const float4*)(g_wcos + b * NN))[tid]; *(float4*)&sw[3][tid * 4] = v;
        v = ((const float4*)(g_wem  + b * NN))[tid]; *(float4*)&sw[4][tid * 4] = v;
    }
    __syncthreads();

    const float4* p4 = (const float4*)(pred_inc + (size_t)row0 * NN);
    const float4* q4 = (const float4*)(pred_inc + (size_t)(row0 + 1) * NN);
    uint2* hp = (uint2*)(g_ah + (size_t)row0 * NN);
    uint2* hq = (uint2*)(g_ah + (size_t)(row0 + 1) * NN);

    float a0 = 0.f, a1 = 0.f, a2 = 0.f, a3 = 0.f, a4 = 0.f;
    float b0 = 0.f, b1 = 0.f, b2 = 0.f, b3 = 0.f, b4 = 0.f;
    #pragma unroll 4
    for (int i = lane; i < NN / 4; i += 32) {
        float4 p = p4[i];
        float4 q = q4[i];
        {
            __half2 h0 = __floats2half2_rn(p.x, p.y);
            __half2 h1 = __floats2half2_rn(p.z, p.w);
            uint2 st;
            st.x = *(uint32_t*)&h0; st.y = *(uint32_t*)&h1;
            hp[i] = st;
            __half2 g0 = __floats2half2_rn(q.x, q.y);
            __half2 g1 = __floats2half2_rn(q.z, q.w);
            st.x = *(uint32_t*)&g0; st.y = *(uint32_t*)&g1;
            hq[i] = st;
        }
        float4 w = *(const float4*)&sw[0][i * 4];
        a0 = fmaf(p.x, w.x, a0); a0 = fmaf(p.y, w.y, a0);
        a0 = fmaf(p.z, w.z, a0); a0 = fmaf(p.w, w.w, a0);
        b0 = fmaf(q.x, w.x, b0); b0 = fmaf(q.y, w.y, b0);
        b0 = fmaf(q.z, w.z, b0); b0 = fmaf(q.w, w.w, b0);
        float4 e = *(const float4*)&sw[1][i * 4];
        a1 = fmaf(p.x, e.x, a1); a1 = fmaf(p.y, e.y, a1);
        a1 = fmaf(p.z, e.z, a1); a1 = fmaf(p.w, e.w, a1);
        b1 = fmaf(q.x, e.x, b1); b1 = fmaf(q.y, e.y, b1);
        b1 = fmaf(q.z, e.z, b1); b1 = fmaf(q.w, e.w, b1);
        float4 s = *(const float4*)&sw[2][i * 4];
        a2 = fmaf(p.x, s.x, a2); a2 = fmaf(p.y, s.y, a2);
        a2 = fmaf(p.z, s.z, a2); a2 = fmaf(p.w, s.w, a2);
        b2 = fmaf(q.x, s.x, b2); b2 = fmaf(q.y, s.y, b2);
        b2 = fmaf(q.z, s.z, b2); b2 = fmaf(q.w, s.w, b2);
        float4 c = *(const float4*)&sw[3][i * 4];
        a3 = fmaf(p.x, c.x, a3); a3 = fmaf(p.y, c.y, a3);
        a3 = fmaf(p.z, c.z, a3); a3 = fmaf(p.w, c.w, a3);
        b3 = fmaf(q.x, c.x, b3); b3 = fmaf(q.y, c.y, b3);
        b3 = fmaf(q.z, c.z, b3); b3 = fmaf(q.w, c.w, b3);
        float4 m = *(const float4*)&sw[4][i * 4];
        a4 = fmaf(p.x, m.x, a4); a4 = fmaf(p.y, m.y, a4);
        a4 = fmaf(p.z, m.z, a4); a4 = fmaf(p.w, m.w, a4);
        b4 = fmaf(q.x, m.x, b4); b4 = fmaf(q.y, m.y, b4);
        b4 = fmaf(q.z, m.z, b4); b4 = fmaf(q.w, m.w, b4);
    }
    #pragma unroll
    for (int o = 16; o > 0; o >>= 1) {
        a0 += __shfl_xor_sync(0xFFFFFFFFu, a0, o);
        a1 += __shfl_xor_sync(0xFFFFFFFFu, a1, o);
        a2 += __shfl_xor_sync(0xFFFFFFFFu, a2, o);
        a3 += __shfl_xor_sync(0xFFFFFFFFu, a3, o);
        a4 += __shfl_xor_sync(0xFFFFFFFFu, a4, o);
        b0 += __shfl_xor_sync(0xFFFFFFFFu, b0, o);
        b1 += __shfl_xor_sync(0xFFFFFFFFu, b1, o);
        b2 += __shfl_xor_sync(0xFFFFFFFFu, b2, o);
        b3 += __shfl_xor_sync(0xFFFFFFFFu, b3, o);
        b4 += __shfl_xor_sync(0xFFFFFFFFu, b4, o);
    }
    if (lane == 0) {
        #pragma unroll
        for (int rr = 0; rr < 2; rr++) {
            int   row = row0 + rr;
            int   h   = row % HH;
            float s0  = rr ? b0 : a0;
            float s1  = rr ? b1 : a1;
            float s2  = rr ? b2 : a2;
            float s3  = rr ? b3 : a3;
            float s4v = rr ? b4 : a4;

            float inv = 1.f / (s0 + EPSV);
            bool  pc  = (h < NN) && (is_track[b * NN + h] != 0);
            float nm  = pc ? 0.f : 1.f;

            float ke  = log1pf(fmaxf(s0, 0.f));
            float eta = s1 * inv * (1.f / 3.0f);
            float ph  = atan2f(s2 * inv, s3 * inv);
            float em  = s4v * inv;

            long long r3 = (long long)row * 3;
            float cpt = 0.f, ceta = 0.f, cphi = 0.f;
            if (pc) {
                cpt  = track_pt [b * NN + h];
                ceta = track_eta[b * NN + h];
                cphi = track_phi[b * NN + h];
            }
            out[OFF_CH + r3 + 0] = cpt;
            out[OFF_CH + r3 + 1] = ceta;
            out[OFF_CH + r3 + 2] = cphi;
            out[OFF_NEUT + r3 + 0] = ke  * nm;
            out[OFF_NEUT + r3 + 1] = eta * nm;
            out[OFF_NEUT + r3 + 2] = ph  * nm;
            out[OFF_PC + row] = pc ? 1.f : 0.f;
            out[OFF_EM + row] = em;
        }
    }
}

// ---------------------------------------------------------------------------
// 4) fp16 mma GEMM with ldmatrix: block 128x128, BK=64 halfs, 128 threads
//    (4 warps, 2x2, warp tile 64x64). 2-stage cp.async, dynamic smem 72 KB.
// ---------------------------------------------------------------------------
#define BM 128
#define BN 128
#define BKH 64
#define KPAD 72                     // halfs per smem row (144 B)
#define A_H (BM * KPAD)             // 9216 halfs
#define B_H (BN * KPAD)
#define STG_H (A_H + B_H)           // 18432 halfs = 36 KB / stage
#define GEMM_SMEM (2 * STG_H * 2)   // 73728 B

__global__ __launch_bounds__(128)
void gemm_mma_kernel(float* __restrict__ C) {   // [B][H][D]
    extern __shared__ __align__(16) __half smem[];

    int tid  = threadIdx.x;
    int wid  = tid >> 5;
    int lane = tid & 31;
    int gid  = lane >> 2;
    int tig  = lane & 3;
    int warp_m = wid & 1;
    int warp_n = wid >> 1;
    int q  = lane >> 3;   // ldmatrix quadrant
    int rr = lane & 7;

    int b  = blockIdx.z;
    int m0 = blockIdx.y * BM;
    int n0 = blockIdx.x * BN;

    const __half* Ah = g_ah + ((size_t)b * HH + m0) * NN;
    const __half* Bh = g_bh + ((size_t)b * DD + n0) * NN;

    int lr = tid >> 3;   // 0..15 (+16 per pass, 8 passes over 128 rows)
    int lj = tid & 7;    // 8-half chunk within 64-half row

    uint32_t a_off = (uint32_t)(((warp_m * 64 + (q & 1) * 8 + rr) * KPAD + (q >> 1) * 8) * 2);
    uint32_t b_off = (uint32_t)(((warp_n * 64 + (q >> 1) * 8 + rr) * KPAD + (q & 1) * 8) * 2);

    float acc[4][8][4];
    #pragma unroll
    for (int i = 0; i < 4; i++)
        #pragma unroll
        for (int j = 0; j < 8; j++)
            #pragma unroll
            for (int k = 0; k < 4; k++) acc[i][j][k] = 0.f;

    auto load_tile = [&](int t, int s) {
        __half* asx = smem + s * STG_H;
        __half* bsx = asx + A_H;
        int k0 = t * BKH;
        #pragma unroll
        for (int i = 0; i < 8; i++) {
            int r = lr + i * 16;
            cp16(smem_u32(asx + r * KPAD + lj * 8), Ah + (size_t)r * NN + k0 + lj * 8);
            cp16(smem_u32(bsx + r * KPAD + lj * 8), Bh + (size_t)r * NN + k0 + lj * 8);
        }
        cp_commit();
    };

    load_tile(0, 0);

    const int NT = NN / BKH;  // 16
    for (int t = 0; t < NT; t++) {
        if (t + 1 < NT) {
            load_tile(t + 1, (t + 1) & 1);
            cp_wait<1>();
        } else {
            cp_wait<0>();
        }
        __syncthreads();

        uint32_t as_u = smem_u32(smem + (t & 1) * STG_H);
        uint32_t bs_u = as_u + A_H * 2;

        #pragma unroll
        for (int kk = 0; kk < BKH; kk += 16) {
            uint32_t bf[8][2];
            #pragma unroll
            for (int nf2 = 0; nf2 < 4; nf2++) {
                uint32_t r0, r1, r2, r3;
                LDSM_X4(r0, r1, r2, r3,
                        bs_u + b_off + (uint32_t)((nf2 * 16 * KPAD + kk) * 2));
                bf[2 * nf2][0]     = r0;
                bf[2 * nf2][1]     = r1;
                bf[2 * nf2 + 1][0] = r2;
                bf[2 * nf2 + 1][1] = r3;
            }
            #pragma unroll
            for (int mf = 0; mf < 4; mf++) {
                uint32_t af[4];
                LDSM_X4(af[0], af[1], af[2], af[3],
                        as_u + a_off + (uint32_t)((mf * 16 * KPAD + kk) * 2));
                #pragma unroll
                for (int nf = 0; nf < 8; nf++)
                    mma_f16(acc[mf][nf], af, bf[nf]);
            }
        }
        __syncthreads();
    }

    // Epilogue
    float* Cb = C + ((size_t)b * HH + m0) * DD + n0;
    #pragma unroll
    for (int mf = 0; mf < 4; mf++) {
        int r0 = warp_m * 64 + mf * 16 + gid;
        #pragma unroll
        for (int nf = 0; nf < 8; nf++) {
            int cc = warp_n * 64 + nf * 8 + tig * 2;
            *(float2*)(Cb + (size_t)r0 * DD + cc) =
                make_float2(acc[mf][nf][0], acc[mf][nf][1]);
            *(float2*)(Cb + (size_t)(r0 + 8) * DD + cc) =
                make_float2(acc[mf][nf][2], acc[mf][nf][3]);
        }
    }
}

// ---------------------------------------------------------------------------
extern "C" void kernel_launch(void* const* d_in, const int* in_sizes, int n_in,
                              void* d_out, int out_size) {
    const float* pred_inc  = (const float*)d_in[0];
    const float* node_feat = (const float*)d_in[1];
    const float* e_raw     = (const float*)d_in[2];
    const float* eta_raw   = (const float*)d_in[3];
    const float* phi       = (const float*)d_in[4];
    const float* em_frac   = (const float*)d_in[5];
    const float* track_pt  = (const float*)d_in[6];
    const float* track_eta = (const float*)d_in[7];
    const float* track_phi = (const float*)d_in[8];
    const int*   is_track  = (const int*)d_in[9];
    const int*   is_topo   = (const int*)d_in[10];
    float* out = (float*)d_out;

    cudaFuncSetAttribute(gemm_mma_kernel,
                         cudaFuncAttributeMaxDynamicSharedMemorySize, GEMM_SMEM);

    prep_kernel<<<(BB * NN + 255) / 256, 256>>>(e_raw, eta_raw, phi, em_frac, is_topo);

    {
        dim3 grid(NN / 32, DD / 32, BB);
        transpose_kernel<<<grid, dim3(32, 8)>>>(node_feat);
    }
    nfs_final_kernel<<<BB, DD>>>(out);

    {
        dim3 grid(HH / 16, BB);
        row_kernel<<<grid, 256>>>(pred_inc, track_pt, track_eta,
                                  track_phi, is_track, out);
    }

    {
        dim3 grid(DD / BN, HH / BM, BB);
        gemm_mma_kernel<<<grid, 128, GEMM_SMEM>>>(out + OFF_MM);
    }
}